// round 7
// baseline (speedup 1.0000x reference)
#include <cuda_runtime.h>

// TT-embedding:
//   core0: (1,8,40,16)    A[x][p][b]     idx = x*640 + p*16 + b
//   core1: (16,8,32,16)   M[b][y][q][c]  idx = b*4096 + y*512 + q*16 + c
//   core2: (16,16,25,1)   C[c][z][r]     idx = c*400 + z*25 + r
//   id -> p = id/800, q = (id%800)/25, r = id%25
//   out[tok][x*128+y*16+z] = sum_{b,c} A[x][p][b] M[b][y][q][c] C[c][z][r]
//
// Stage 1: s[p*32+q][c][xy] = sum_b A[x][p][b] * M[b][y][q][c]   (5.2 MB, L2)
//          c2t[r][c][z]     = core2 transposed                    (25.6 KB)
// Stage 2: out[tok][xy][z] = sum_c s[pq][c][xy] * c2t[r][c][z]
//          2 tokens/warp, 16 lanes/token, 4 xy rows/lane, f32x2 FMA.
//          s-row loads software-pipelined (4-deep double buffer), first
//          batch issued before the smem fill to hide L2 latency.

#define NTOK 16384
typedef unsigned long long ull;

__device__ float g_s[1280 * 1024];
__device__ __align__(16) float g_c2t[6400];
__device__ int g_ids64;

// ---------------------------------------------------------------------------
// Stage 1: build s table (+ c2t transpose + id-width sniff in block 0)
// ---------------------------------------------------------------------------
__global__ __launch_bounds__(256) void build_s(const float* __restrict__ c0,
                                               const float* __restrict__ c1,
                                               const float* __restrict__ c2,
                                               const int* __restrict__ ids) {
    int pq = blockIdx.x;
    int p = pq >> 5, q = pq & 31;

    __shared__ float sA[128];    // [x][b]
    __shared__ float sM[2048];   // [b][y][c]

    int t = threadIdx.x;
    if (t < 128) {
        int x = t >> 4, b = t & 15;
        sA[t] = c0[x * 640 + p * 16 + b];
    }
    for (int i = t; i < 2048; i += 256) {
        int b = i >> 7, y = (i >> 4) & 7, cc = i & 15;
        sM[i] = c1[b * 4096 + y * 512 + q * 16 + cc];
    }
    __syncthreads();

    for (int o = t; o < 1024; o += 256) {
        int cc = o >> 6, xy = o & 63;
        int x = xy >> 3, y = xy & 7;
        float acc = 0.f;
#pragma unroll
        for (int b = 0; b < 16; ++b)
            acc += sA[x * 16 + b] * sM[b * 128 + y * 16 + cc];
        g_s[pq * 1024 + o] = acc;
    }

    if (pq == 0) {
        for (int i = t; i < 6400; i += 256) {
            int r = i >> 8, cz = i & 255;
            int cc = cz >> 4, z = cz & 15;
            g_c2t[i] = c2[cc * 400 + z * 25 + r];
        }
        if (t == 0) {
            int ored = 0;
#pragma unroll
            for (int i = 0; i < 32; ++i) ored |= ids[2 * i + 1];
            g_ids64 = (ored == 0) ? 1 : 0;
        }
    }
}

// ---------------------------------------------------------------------------
// Stage 2
// ---------------------------------------------------------------------------
__global__ __launch_bounds__(256, 2) void tt_gather(const int* __restrict__ ids,
                                                    float* __restrict__ out) {
    __shared__ __align__(16) float Cs[6400];   // c2t copy [r][c][z]
    int t = threadIdx.x;
    int lane = t & 31, warp = t >> 5;
    int half = lane >> 4, j = lane & 15;
    int tok = (blockIdx.x * 8 + warp) * 2 + half;

    // --- compute indices + launch first s-load batch BEFORE smem fill ---
    int id = g_ids64 ? __ldg(ids + 2 * tok) : __ldg(ids + tok);
    int p = id / 800;
    int rem = id - p * 800;
    int q = rem / 25;
    int r = rem - q * 25;

    const float4* srow =
        reinterpret_cast<const float4*>(g_s + (p * 32 + q) * 1024) + j;

    float4 cur[4], nxt[4];
#pragma unroll
    for (int i = 0; i < 4; ++i) cur[i] = __ldg(srow + i * 16);

    // --- fill Cs while those loads are in flight ---
    {
        const float4* src = reinterpret_cast<const float4*>(g_c2t);
        float4* dst = reinterpret_cast<float4*>(Cs);
        for (int i = t; i < 1600; i += 256) dst[i] = src[i];
    }
    __syncthreads();

    const ulonglong2* crow = reinterpret_cast<const ulonglong2*>(Cs + r * 256);

    ull acc[4][8];   // [xy row i][z-pair k]
#pragma unroll
    for (int i = 0; i < 4; ++i)
#pragma unroll
        for (int k = 0; k < 8; ++k) acc[i][k] = 0ull;

#pragma unroll
    for (int cb = 0; cb < 4; ++cb) {          // c batches of 4
        if (cb < 3) {
#pragma unroll
            for (int i = 0; i < 4; ++i)
                nxt[i] = __ldg(srow + (cb * 4 + 4 + i) * 16);
        }
#pragma unroll
        for (int cj = 0; cj < 4; ++cj) {
            int c = cb * 4 + cj;
            float4 sv = cur[cj];
            ull s0, s1, s2, s3;
            asm("mov.b64 %0,{%1,%1};" : "=l"(s0) : "f"(sv.x));
            asm("mov.b64 %0,{%1,%1};" : "=l"(s1) : "f"(sv.y));
            asm("mov.b64 %0,{%1,%1};" : "=l"(s2) : "f"(sv.z));
            asm("mov.b64 %0,{%1,%1};" : "=l"(s3) : "f"(sv.w));
#pragma unroll
            for (int k4 = 0; k4 < 4; ++k4) {
                ulonglong2 cv = crow[c * 4 + k4];   // z pairs 2*k4, 2*k4+1
                asm("fma.rn.f32x2 %0,%1,%2,%0;" : "+l"(acc[0][2*k4])   : "l"(s0), "l"(cv.x));
                asm("fma.rn.f32x2 %0,%1,%2,%0;" : "+l"(acc[0][2*k4+1]) : "l"(s0), "l"(cv.y));
                asm("fma.rn.f32x2 %0,%1,%2,%0;" : "+l"(acc[1][2*k4])   : "l"(s1), "l"(cv.x));
                asm("fma.rn.f32x2 %0,%1,%2,%0;" : "+l"(acc[1][2*k4+1]) : "l"(s1), "l"(cv.y));
                asm("fma.rn.f32x2 %0,%1,%2,%0;" : "+l"(acc[2][2*k4])   : "l"(s2), "l"(cv.x));
                asm("fma.rn.f32x2 %0,%1,%2,%0;" : "+l"(acc[2][2*k4+1]) : "l"(s2), "l"(cv.y));
                asm("fma.rn.f32x2 %0,%1,%2,%0;" : "+l"(acc[3][2*k4])   : "l"(s3), "l"(cv.x));
                asm("fma.rn.f32x2 %0,%1,%2,%0;" : "+l"(acc[3][2*k4+1]) : "l"(s3), "l"(cv.y));
            }
        }
#pragma unroll
        for (int i = 0; i < 4; ++i) cur[i] = nxt[i];
    }

    // lane writes rows 4j..4j+3 (16 floats each) of its token
    ulonglong2* o2 = reinterpret_cast<ulonglong2*>(
        out + (size_t)tok * 1024 + j * 64);
#pragma unroll
    for (int i = 0; i < 4; ++i)
#pragma unroll
        for (int k4 = 0; k4 < 4; ++k4)
            o2[i * 4 + k4] = make_ulonglong2(acc[i][2*k4], acc[i][2*k4+1]);
}

// ---------------------------------------------------------------------------
extern "C" void kernel_launch(void* const* d_in, const int* in_sizes, int n_in,
                              void* d_out, int out_size) {
    const float* core0 = (const float*)d_in[0];
    const float* core1 = (const float*)d_in[1];
    const float* core2 = (const float*)d_in[2];
    const int*   ids   = (const int*)d_in[3];
    float* out = (float*)d_out;

    build_s<<<1280, 256>>>(core0, core1, core2, ids);
    tt_gather<<<1024, 256>>>(ids, out);
}

// round 8
// speedup vs baseline: 1.0492x; 1.0492x over previous
#include <cuda_runtime.h>

// TT-embedding:
//   core0: (1,8,40,16)    A[x][p][b]     idx = x*640 + p*16 + b
//   core1: (16,8,32,16)   M[b][y][q][c]  idx = b*4096 + y*512 + q*16 + c
//   core2: (16,16,25,1)   C[c][z][r]     idx = c*400 + z*25 + r
//   id -> p = id/800, q = (id%800)/25, r = id%25
//   out[tok][xy*16+z] = sum_c s[pq][c][xy] * c2t[r][c][z]
//
// Stage 1: s stored PERMUTED: g_s[pq][c][a*8+m] = s[pq][c][xy], a=xy&7, m=xy>>3
// Stage 2: 1 token/warp; lane j: a=j>>2 owns rows {8m+a}, zq=j&3 owns z 4zq..4zq+3.
//   -> stores perfectly coalesced (lane j writes base + j*16B), 4 wf per STG
//   -> s reads: 2 broadcast-group LDG.128 per c, lines fully consumed
//   -> c2t: 1 conflict-free LDS.128 per c per lane (16B z-quad)

#define NTOK 16384
typedef unsigned long long ull;

__device__ float g_s[1280 * 1024];
__device__ __align__(16) float g_c2t[6400];
__device__ int g_ids64;

// ---------------------------------------------------------------------------
// Stage 1: build s table (+ c2t transpose + id-width sniff in block 0)
// ---------------------------------------------------------------------------
__global__ __launch_bounds__(256) void build_s(const float* __restrict__ c0,
                                               const float* __restrict__ c1,
                                               const float* __restrict__ c2,
                                               const int* __restrict__ ids) {
    int pq = blockIdx.x;
    int p = pq >> 5, q = pq & 31;

    __shared__ float sA[128];    // [x][b]
    __shared__ float sM[2048];   // [b][y][c]

    int t = threadIdx.x;
    if (t < 128) {
        int x = t >> 4, b = t & 15;
        sA[t] = c0[x * 640 + p * 16 + b];
    }
    for (int i = t; i < 2048; i += 256) {
        int b = i >> 7, y = (i >> 4) & 7, cc = i & 15;
        sM[i] = c1[b * 4096 + y * 512 + q * 16 + cc];
    }
    __syncthreads();

    for (int o = t; o < 1024; o += 256) {
        int cc = o >> 6, xy = o & 63;
        int x = xy >> 3, y = xy & 7;
        float acc = 0.f;
#pragma unroll
        for (int b = 0; b < 16; ++b)
            acc += sA[x * 16 + b] * sM[b * 128 + y * 16 + cc];
        // permuted write: [c][a][m], a = xy&7, m = xy>>3
        g_s[pq * 1024 + cc * 64 + ((xy & 7) << 3) + (xy >> 3)] = acc;
    }

    if (pq == 0) {
        for (int i = t; i < 6400; i += 256) {
            int r = i >> 8, cz = i & 255;
            int cc = cz >> 4, z = cz & 15;
            g_c2t[i] = c2[cc * 400 + z * 25 + r];
        }
        if (t == 0) {
            int ored = 0;
#pragma unroll
            for (int i = 0; i < 32; ++i) ored |= ids[2 * i + 1];
            g_ids64 = (ored == 0) ? 1 : 0;
        }
    }
}

// ---------------------------------------------------------------------------
// Stage 2: 1 token/warp. lane j: a=j>>2, zq=j&3; owns rows 8m+a, z 4zq..4zq+3.
// ---------------------------------------------------------------------------
__global__ __launch_bounds__(256, 3) void tt_gather(const int* __restrict__ ids,
                                                    float* __restrict__ out) {
    __shared__ __align__(16) float Cs[6400];   // c2t copy [r][c][z]
    int t = threadIdx.x;
    int lane = t & 31, warp = t >> 5;
    int tok = blockIdx.x * 8 + warp;

    int id = g_ids64 ? __ldg(ids + 2 * tok) : __ldg(ids + tok);
    int p = id / 800;
    int rem = id - p * 800;
    int q = rem / 25;
    int r = rem - q * 25;

    int a = lane >> 2, zq = lane & 3;
    const float* srow = g_s + (p * 32 + q) * 1024 + a * 8;   // + c*64

    {
        const float4* src = reinterpret_cast<const float4*>(g_c2t);
        float4* dst = reinterpret_cast<float4*>(Cs);
        for (int i = t; i < 1600; i += 256) dst[i] = src[i];
    }
    __syncthreads();

    // lane's c2t chunk per c: Cs[r*256 + c*16 + zq*4], 16B
    const ulonglong2* crow =
        reinterpret_cast<const ulonglong2*>(Cs + r * 256 + zq * 4);

    ull acc0[8], acc1[8];   // acc0 = z pair (4zq,4zq+1), acc1 = (4zq+2,4zq+3)
#pragma unroll
    for (int m = 0; m < 8; ++m) { acc0[m] = 0ull; acc1[m] = 0ull; }

#pragma unroll
    for (int c = 0; c < 16; ++c) {
        const float4* sp4 = reinterpret_cast<const float4*>(srow + c * 64);
        float4 sv0 = __ldg(sp4);       // m = 0..3
        float4 sv1 = __ldg(sp4 + 1);   // m = 4..7
        ulonglong2 cv = crow[c * 4];   // this lane's 16B of c2t[r][c]

        ull b0, b1, b2, b3, b4, b5, b6, b7;
        asm("mov.b64 %0,{%1,%1};" : "=l"(b0) : "f"(sv0.x));
        asm("mov.b64 %0,{%1,%1};" : "=l"(b1) : "f"(sv0.y));
        asm("mov.b64 %0,{%1,%1};" : "=l"(b2) : "f"(sv0.z));
        asm("mov.b64 %0,{%1,%1};" : "=l"(b3) : "f"(sv0.w));
        asm("mov.b64 %0,{%1,%1};" : "=l"(b4) : "f"(sv1.x));
        asm("mov.b64 %0,{%1,%1};" : "=l"(b5) : "f"(sv1.y));
        asm("mov.b64 %0,{%1,%1};" : "=l"(b6) : "f"(sv1.z));
        asm("mov.b64 %0,{%1,%1};" : "=l"(b7) : "f"(sv1.w));

        asm("fma.rn.f32x2 %0,%1,%2,%0;" : "+l"(acc0[0]) : "l"(b0), "l"(cv.x));
        asm("fma.rn.f32x2 %0,%1,%2,%0;" : "+l"(acc1[0]) : "l"(b0), "l"(cv.y));
        asm("fma.rn.f32x2 %0,%1,%2,%0;" : "+l"(acc0[1]) : "l"(b1), "l"(cv.x));
        asm("fma.rn.f32x2 %0,%1,%2,%0;" : "+l"(acc1[1]) : "l"(b1), "l"(cv.y));
        asm("fma.rn.f32x2 %0,%1,%2,%0;" : "+l"(acc0[2]) : "l"(b2), "l"(cv.x));
        asm("fma.rn.f32x2 %0,%1,%2,%0;" : "+l"(acc1[2]) : "l"(b2), "l"(cv.y));
        asm("fma.rn.f32x2 %0,%1,%2,%0;" : "+l"(acc0[3]) : "l"(b3), "l"(cv.x));
        asm("fma.rn.f32x2 %0,%1,%2,%0;" : "+l"(acc1[3]) : "l"(b3), "l"(cv.y));
        asm("fma.rn.f32x2 %0,%1,%2,%0;" : "+l"(acc0[4]) : "l"(b4), "l"(cv.x));
        asm("fma.rn.f32x2 %0,%1,%2,%0;" : "+l"(acc1[4]) : "l"(b4), "l"(cv.y));
        asm("fma.rn.f32x2 %0,%1,%2,%0;" : "+l"(acc0[5]) : "l"(b5), "l"(cv.x));
        asm("fma.rn.f32x2 %0,%1,%2,%0;" : "+l"(acc1[5]) : "l"(b5), "l"(cv.y));
        asm("fma.rn.f32x2 %0,%1,%2,%0;" : "+l"(acc0[6]) : "l"(b6), "l"(cv.x));
        asm("fma.rn.f32x2 %0,%1,%2,%0;" : "+l"(acc1[6]) : "l"(b6), "l"(cv.y));
        asm("fma.rn.f32x2 %0,%1,%2,%0;" : "+l"(acc0[7]) : "l"(b7), "l"(cv.x));
        asm("fma.rn.f32x2 %0,%1,%2,%0;" : "+l"(acc1[7]) : "l"(b7), "l"(cv.y));
    }

    // stores: lane j writes 16B at base + m*512B + j*16B -> fully coalesced
    float* obase = out + (size_t)tok * 1024 + lane * 4;
#pragma unroll
    for (int m = 0; m < 8; ++m)
        *reinterpret_cast<ulonglong2*>(obase + m * 128) =
            make_ulonglong2(acc0[m], acc1[m]);
}

// ---------------------------------------------------------------------------
extern "C" void kernel_launch(void* const* d_in, const int* in_sizes, int n_in,
                              void* d_out, int out_size) {
    const float* core0 = (const float*)d_in[0];
    const float* core1 = (const float*)d_in[1];
    const float* core2 = (const float*)d_in[2];
    const int*   ids   = (const int*)d_in[3];
    float* out = (float*)d_out;

    build_s<<<1280, 256>>>(core0, core1, core2, ids);
    tt_gather<<<NTOK / 8, 256>>>(ids, out);
}

// round 11
// speedup vs baseline: 1.3339x; 1.2714x over previous
#include <cuda_runtime.h>

// TT-embedding — single persistent kernel.
//   core0: (1,8,40,16)    A[x][p][b]     idx = x*640 + p*16 + b
//   core1: (16,8,32,16)   M[b][y][q][c]  idx = b*4096 + y*512 + q*16 + c
//   core2: (16,16,25,1)   C[c][z][r]     idx = c*400 + z*25 + r
//   id -> p = id/800, q = (id%800)/25, r = id%25
//   out[tok][xy*16+z] = sum_c s[pq][c][xy] * c2t[r][c][z]
//
// Phase A: per-block c2 transpose into smem + strided build of permuted
//   s rows g_s[pq][c][a*8+m] (a=xy&7, m=xy>>3).
// Grid barrier: epoch-ticket atomic (monotonic -> graph-replay safe).
// Phase B: gather, 1 token/warp/iter; plain coherent g_s loads.
//   (R9/R10 bug was Cs addressing: r*256 floats = r*64 ulonglong2, NOT r*32.
//    Reverted to the R8-proven direct expression.)
//
// GRID=444 = 148 SMs x 3; __launch_bounds__(256,3) guarantees co-residency
// (regs<=85, smem ~34KB x 3 = 102KB) -> barrier cannot deadlock.

#define NTOK   16384
#define GRID   444
#define NROWS  1280
typedef unsigned long long ull;

__device__ float g_s[NROWS * 1024];
__device__ unsigned g_bar;   // monotonic epoch counter (never reset)

__global__ __launch_bounds__(256, 3) void tt_fused(const float* __restrict__ c0,
                                                   const float* __restrict__ c1,
                                                   const float* __restrict__ c2,
                                                   const int* __restrict__ ids,
                                                   float* __restrict__ out) {
    __shared__ __align__(16) float Cs[6400];   // c2t [r][c][z]
    __shared__ float sA[128];                  // [x][b]
    __shared__ float sM[2048];                 // [b][y][c]
    __shared__ int sIds64;

    int t = threadIdx.x;
    int bid = blockIdx.x;

    // ---- Phase A0: c2 transpose into this block's smem ----
    for (int i = t; i < 6400; i += 256) {
        int r = i >> 8, cz = i & 255;
        int cc = cz >> 4, z = cz & 15;
        Cs[i] = c2[cc * 400 + z * 25 + r];
    }
    if (t == 0) {
        int ored = 0;
#pragma unroll
        for (int i = 0; i < 32; ++i) ored |= ids[2 * i + 1];
        sIds64 = (ored == 0) ? 1 : 0;
    }

    // ---- Phase A1: build this block's s rows (permuted layout) ----
    for (int pq = bid; pq < NROWS; pq += GRID) {
        int p = pq >> 5, q = pq & 31;
        __syncthreads();   // protect sA/sM reuse across iterations
        if (t < 128) {
            int x = t >> 4, b = t & 15;
            sA[t] = c0[x * 640 + p * 16 + b];
        }
        for (int i = t; i < 2048; i += 256) {
            int b = i >> 7, y = (i >> 4) & 7, cc = i & 15;
            sM[i] = c1[b * 4096 + y * 512 + q * 16 + cc];
        }
        __syncthreads();
        for (int o = t; o < 1024; o += 256) {
            int cc = o >> 6, xy = o & 63;
            int x = xy >> 3, y = xy & 7;
            float acc = 0.f;
#pragma unroll
            for (int b = 0; b < 16; ++b)
                acc += sA[x * 16 + b] * sM[b * 128 + y * 16 + cc];
            g_s[pq * 1024 + cc * 64 + ((xy & 7) << 3) + (xy >> 3)] = acc;
        }
    }

    // ---- grid-wide barrier (epoch tickets; replay-safe) ----
    __threadfence();
    __syncthreads();
    if (t == 0) {
        unsigned ticket = atomicAdd(&g_bar, 1u);
        unsigned target = (ticket / GRID + 1u) * GRID;
        while (atomicAdd(&g_bar, 0u) < target) __nanosleep(64);
    }
    __syncthreads();
    __threadfence();

    // ---- Phase B: gather ----
    int lane = t & 31, warp = t >> 5;
    int a = lane >> 2, zq = lane & 3;
    int ids64 = sIds64;

    for (int tok = bid * 8 + warp; tok < NTOK; tok += GRID * 8) {
        int id = ids64 ? __ldg(ids + 2 * tok) : __ldg(ids + tok);
        int p = id / 800;
        int rem = id - p * 800;
        int q = rem / 25;
        int r = rem - q * 25;

        // plain coherent loads: g_s was written this launch
        const float4* sp = reinterpret_cast<const float4*>(
            g_s + (p * 32 + q) * 1024 + a * 8);
        // R8-proven addressing: Cs[r*256 + c*16 + zq*4]
        const ulonglong2* cr =
            reinterpret_cast<const ulonglong2*>(Cs + r * 256 + zq * 4);

        ull acc0[8], acc1[8];   // z pairs (4zq,4zq+1) and (4zq+2,4zq+3)
#pragma unroll
        for (int m = 0; m < 8; ++m) { acc0[m] = 0ull; acc1[m] = 0ull; }

#pragma unroll
        for (int c = 0; c < 16; ++c) {
            float4 sv0 = sp[c * 16];       // m = 0..3
            float4 sv1 = sp[c * 16 + 1];   // m = 4..7
            ulonglong2 cv = cr[c * 4];     // this lane's 16B of c2t[r][c]

            ull b0, b1, b2, b3, b4, b5, b6, b7;
            asm("mov.b64 %0,{%1,%1};" : "=l"(b0) : "f"(sv0.x));
            asm("mov.b64 %0,{%1,%1};" : "=l"(b1) : "f"(sv0.y));
            asm("mov.b64 %0,{%1,%1};" : "=l"(b2) : "f"(sv0.z));
            asm("mov.b64 %0,{%1,%1};" : "=l"(b3) : "f"(sv0.w));
            asm("mov.b64 %0,{%1,%1};" : "=l"(b4) : "f"(sv1.x));
            asm("mov.b64 %0,{%1,%1};" : "=l"(b5) : "f"(sv1.y));
            asm("mov.b64 %0,{%1,%1};" : "=l"(b6) : "f"(sv1.z));
            asm("mov.b64 %0,{%1,%1};" : "=l"(b7) : "f"(sv1.w));

            asm("fma.rn.f32x2 %0,%1,%2,%0;" : "+l"(acc0[0]) : "l"(b0), "l"(cv.x));
            asm("fma.rn.f32x2 %0,%1,%2,%0;" : "+l"(acc1[0]) : "l"(b0), "l"(cv.y));
            asm("fma.rn.f32x2 %0,%1,%2,%0;" : "+l"(acc0[1]) : "l"(b1), "l"(cv.x));
            asm("fma.rn.f32x2 %0,%1,%2,%0;" : "+l"(acc1[1]) : "l"(b1), "l"(cv.y));
            asm("fma.rn.f32x2 %0,%1,%2,%0;" : "+l"(acc0[2]) : "l"(b2), "l"(cv.x));
            asm("fma.rn.f32x2 %0,%1,%2,%0;" : "+l"(acc1[2]) : "l"(b2), "l"(cv.y));
            asm("fma.rn.f32x2 %0,%1,%2,%0;" : "+l"(acc0[3]) : "l"(b3), "l"(cv.x));
            asm("fma.rn.f32x2 %0,%1,%2,%0;" : "+l"(acc1[3]) : "l"(b3), "l"(cv.y));
            asm("fma.rn.f32x2 %0,%1,%2,%0;" : "+l"(acc0[4]) : "l"(b4), "l"(cv.x));
            asm("fma.rn.f32x2 %0,%1,%2,%0;" : "+l"(acc1[4]) : "l"(b4), "l"(cv.y));
            asm("fma.rn.f32x2 %0,%1,%2,%0;" : "+l"(acc0[5]) : "l"(b5), "l"(cv.x));
            asm("fma.rn.f32x2 %0,%1,%2,%0;" : "+l"(acc1[5]) : "l"(b5), "l"(cv.y));
            asm("fma.rn.f32x2 %0,%1,%2,%0;" : "+l"(acc0[6]) : "l"(b6), "l"(cv.x));
            asm("fma.rn.f32x2 %0,%1,%2,%0;" : "+l"(acc1[6]) : "l"(b6), "l"(cv.y));
            asm("fma.rn.f32x2 %0,%1,%2,%0;" : "+l"(acc0[7]) : "l"(b7), "l"(cv.x));
            asm("fma.rn.f32x2 %0,%1,%2,%0;" : "+l"(acc1[7]) : "l"(b7), "l"(cv.y));
        }

        float* obase = out + (size_t)tok * 1024 + lane * 4;
#pragma unroll
        for (int m = 0; m < 8; ++m)
            *reinterpret_cast<ulonglong2*>(obase + m * 128) =
                make_ulonglong2(acc0[m], acc1[m]);
    }
}

// ---------------------------------------------------------------------------
extern "C" void kernel_launch(void* const* d_in, const int* in_sizes, int n_in,
                              void* d_out, int out_size) {
    const float* core0 = (const float*)d_in[0];
    const float* core1 = (const float*)d_in[1];
    const float* core2 = (const float*)d_in[2];
    const int*   ids   = (const int*)d_in[3];
    float* out = (float*)d_out;

    tt_fused<<<GRID, 256>>>(core0, core1, core2, ids, out);
}